// round 14
// baseline (speedup 1.0000x reference)
#include <cuda_runtime.h>
#include <cuda_fp16.h>
#include <cstdint>

#define NN 50000
#define EE 640000
#define FIN 768
#define HD 128
#define TOT (EE + NN)
#define NEG_SLOPE 0.2f

// ---------------- scratch (device globals; no allocation allowed) ----------------
__device__ __half   g_xlh[NN * HD];   // xl fp16 (consumer: aggregation)
__device__ float    g_xr[NN * HD];
__device__ __half   g_hA[NN * HD];    // layer outputs fp16
__device__ __half   g_hB[NN * HD];
__device__ uint32_t g_Wh[147456];     // all weights fp16, kpair-interleaved [p][c] c<128:Wl c>=128:Wr
__device__ int      g_counts[NN];
__device__ int      g_local[NN];
__device__ int      g_rowptr[NN + 1];
__device__ int      g_cursor[NN];
__device__ int      g_srcarr[TOT];
__device__ int      g_blocksums[64];
__device__ float    g_pool[HD];

__device__ __forceinline__ __half* bufh(int i) {
    return i == 2 ? g_hA : g_hB;
}

__device__ __forceinline__ uint32_t pack_h2(float a, float b) {
    __half2 h = __floats2half2_rn(a, b);
    return *reinterpret_cast<uint32_t*>(&h);
}

// ---------------- CSR build ----------------
__global__ void k_init() {
    int i = blockIdx.x * blockDim.x + threadIdx.x;
    if (i < NN) g_counts[i] = 1;          // self loop
    if (i < HD) g_pool[i] = 0.f;
}

__global__ void k_hist(const int* __restrict__ ei) {
    int e = blockIdx.x * blockDim.x + threadIdx.x;
    if (e < EE) atomicAdd(&g_counts[ei[EE + e]], 1);
}

__global__ void k_scan_block() {
    __shared__ int sm[1024];
    int i = blockIdx.x * 1024 + threadIdx.x;
    int v = (i < NN) ? g_counts[i] : 0;
    sm[threadIdx.x] = v;
    __syncthreads();
    for (int off = 1; off < 1024; off <<= 1) {
        int t = (threadIdx.x >= off) ? sm[threadIdx.x - off] : 0;
        __syncthreads();
        sm[threadIdx.x] += t;
        __syncthreads();
    }
    if (i < NN) g_local[i] = sm[threadIdx.x] - v;   // exclusive
    if (threadIdx.x == 1023) g_blocksums[blockIdx.x] = sm[1023];
}

__global__ void k_scan_top(int nb) {
    __shared__ int sm[64];
    int t = threadIdx.x;
    int v = (t < nb) ? g_blocksums[t] : 0;
    sm[t] = v;
    __syncthreads();
    for (int off = 1; off < 64; off <<= 1) {
        int u = (t >= off) ? sm[t - off] : 0;
        __syncthreads();
        sm[t] += u;
        __syncthreads();
    }
    if (t < nb) g_blocksums[t] = sm[t] - v;         // exclusive
}

__global__ void k_finalize_csr() {
    int i = blockIdx.x * blockDim.x + threadIdx.x;
    if (i < NN) {
        int off = g_local[i] + g_blocksums[i >> 10];
        g_rowptr[i] = off;
        g_cursor[i] = off + 1;      // slot 0 reserved for self loop
        g_srcarr[off] = i;          // self loop
    }
    if (i == 0) g_rowptr[NN] = TOT;
}

__global__ void k_scatter(const int* __restrict__ ei) {
    int e = blockIdx.x * blockDim.x + threadIdx.x;
    if (e < EE) {
        int s = ei[e];
        int d = ei[EE + e];
        g_srcarr[atomicAdd(&g_cursor[d], 1)] = s;
    }
}

// ---------------- weight conversion: fp32 [K,128]x2 -> fp16 kpair-interleaved [K/2, 256] ----------------
// layer bases (uint32): L1 0 (98304), L2 98304, L3 114688, L4 131072
__global__ void k_wconv(const float* w1l, const float* w1r, const float* w2l, const float* w2r,
                        const float* w3l, const float* w3r, const float* w4l, const float* w4r) {
    int idx = blockIdx.x * blockDim.x + threadIdx.x;   // 147456 threads
    int l, base;
    if      (idx < 98304)  { l = 0; base = 0; }
    else if (idx < 114688) { l = 1; base = 98304; }
    else if (idx < 131072) { l = 2; base = 114688; }
    else                   { l = 3; base = 131072; }
    const float* Wl = (l == 0) ? w1l : (l == 1) ? w2l : (l == 2) ? w3l : w4l;
    const float* Wr = (l == 0) ? w1r : (l == 1) ? w2r : (l == 2) ? w3r : w4r;
    int local = idx - base;
    int p = local >> 8, c = local & 255;
    const float* W = (c < 128) ? Wl : Wr;
    int cc = c & 127;
    float a = W[(2 * p) * 128 + cc];
    float b = W[(2 * p + 1) * 128 + cc];
    g_Wh[idx] = pack_h2(a, b);
}

// ---------------- fp16 dual GEMM: tile M=64, N=256 (B1||B2), A read ONCE ----------------
// ASRC 0: A fp32 external; 1: A fp16 scratch. Outputs: cols 0-127 -> g_xlh, 128-255 -> g_xr.
#define ASTR 12     // uint32 stride; banks 12g+t all-distinct
#define BSTR 264    // 256 cols + 8 pad; 264 mod 32 = 8 -> banks 8t+g all-distinct

template<int ASRC>
__global__ void __launch_bounds__(256, 2)
k_gemm_dual(const float* __restrict__ Aext, int Asel, int wbase, int M, int K) {
    const float*  __restrict__ Af = Aext;
    const __half* __restrict__ Ah = (ASRC == 1) ? bufh(Asel) : nullptr;
    const uint32_t* __restrict__ Bsrc = g_Wh + wbase;

    __shared__ uint32_t As[2][64 * ASTR];   // 64 rows x 8 half2 (k16)
    __shared__ uint32_t Bs[2][8 * BSTR];    // 8 kpairs x 256 half2 (+pad)

    const int tid  = threadIdx.x;
    const int wid  = tid >> 5;
    const int lane = tid & 31;
    const int g = lane >> 2;
    const int t = lane & 3;
    const int warpM = wid & 1;   // 2 warps in M (32 rows each)
    const int warpN = wid >> 1;  // 4 warps in N (64 cols each)
    const int row0 = blockIdx.x * 64;

    float acc[2][8][4];
    #pragma unroll
    for (int i = 0; i < 2; i++)
        #pragma unroll
        for (int j = 0; j < 8; j++)
            #pragma unroll
            for (int k = 0; k < 4; k++) acc[i][j][k] = 0.f;

    // staging registers
    float4 raf;
    uint2  rah;
    uint4  rbu[2];

    const int arow = tid >> 2;            // 0..63
    const int aq   = (tid & 3) * 2;       // half2 index 0,2,4,6
    const int gr   = row0 + arow;
    const bool aok = (gr < M);

    auto loadA = [&](int k0) {
        if (ASRC == 0) {
            raf = aok ? *reinterpret_cast<const float4*>(&Af[(size_t)gr * K + k0 + 2 * aq])
                      : make_float4(0.f, 0.f, 0.f, 0.f);
        } else {
            rah = aok ? *reinterpret_cast<const uint2*>(&Ah[(size_t)gr * K + k0 + 2 * aq])
                      : make_uint2(0u, 0u);
        }
    };
    auto storeA = [&](int bi) {
        uint2 h;
        if (ASRC == 0) { h.x = pack_h2(raf.x, raf.y); h.y = pack_h2(raf.z, raf.w); }
        else           { h = rah; }
        *reinterpret_cast<uint2*>(&As[bi][arow * ASTR + aq]) = h;
    };
    auto loadB = [&](int k0) {
        const int pbase = k0 >> 1;
        #pragma unroll
        for (int i = 0; i < 2; i++) {
            int s = tid + i * 256;
            int p = s >> 6, c4 = s & 63;
            rbu[i] = *reinterpret_cast<const uint4*>(&Bsrc[(size_t)(pbase + p) * 256 + c4 * 4]);
        }
    };
    auto storeB = [&](int bi) {
        #pragma unroll
        for (int i = 0; i < 2; i++) {
            int s = tid + i * 256;
            int p = s >> 6, c4 = s & 63;
            *reinterpret_cast<uint4*>(&Bs[bi][p * BSTR + c4 * 4]) = rbu[i];
        }
    };

    // ---- chunk 0 ----
    loadA(0); loadB(0);
    storeA(0); storeB(0);
    __syncthreads();

    const int niter = K >> 4;    // k-chunk 16
    int cur = 0;
    for (int it = 0; it < niter; it++) {
        const bool has_next = (it + 1 < niter);
        if (has_next) { loadA((it + 1) << 4); loadB((it + 1) << 4); }

        const uint32_t* __restrict__ Ab = As[cur];
        const uint32_t* __restrict__ Bb = Bs[cur];
        uint32_t af[2][4];
        #pragma unroll
        for (int mt = 0; mt < 2; mt++) {
            int rowb = warpM * 32 + mt * 16;
            af[mt][0] = Ab[(rowb + g)     * ASTR + t];
            af[mt][1] = Ab[(rowb + g + 8) * ASTR + t];
            af[mt][2] = Ab[(rowb + g)     * ASTR + t + 4];
            af[mt][3] = Ab[(rowb + g + 8) * ASTR + t + 4];
        }
        uint32_t bf[8][2];
        #pragma unroll
        for (int nt = 0; nt < 8; nt++) {
            int nbase = warpN * 64 + nt * 8;
            bf[nt][0] = Bb[t * BSTR + nbase + g];
            bf[nt][1] = Bb[(t + 4) * BSTR + nbase + g];
        }
        #pragma unroll
        for (int mt = 0; mt < 2; mt++)
            #pragma unroll
            for (int nt = 0; nt < 8; nt++) {
                asm volatile(
                    "mma.sync.aligned.m16n8k16.row.col.f32.f16.f16.f32 "
                    "{%0,%1,%2,%3}, {%4,%5,%6,%7}, {%8,%9}, {%0,%1,%2,%3};"
                    : "+f"(acc[mt][nt][0]), "+f"(acc[mt][nt][1]),
                      "+f"(acc[mt][nt][2]), "+f"(acc[mt][nt][3])
                    : "r"(af[mt][0]), "r"(af[mt][1]), "r"(af[mt][2]), "r"(af[mt][3]),
                      "r"(bf[nt][0]), "r"(bf[nt][1]));
            }

        if (has_next) { storeA(cur ^ 1); storeB(cur ^ 1); }
        __syncthreads();
        cur ^= 1;
    }

    // epilogue: warpN 0,1 -> g_xlh (fp16); warpN 2,3 -> g_xr (fp32)
    #pragma unroll
    for (int mt = 0; mt < 2; mt++) {
        int r0 = row0 + warpM * 32 + mt * 16 + g;
        #pragma unroll
        for (int nt = 0; nt < 8; nt++) {
            int c = warpN * 64 + nt * 8 + t * 2;
            if (c < 128) {
                if (r0 < M)
                    *reinterpret_cast<uint32_t*>(&g_xlh[(size_t)r0 * 128 + c]) =
                        pack_h2(acc[mt][nt][0], acc[mt][nt][1]);
                if (r0 + 8 < M)
                    *reinterpret_cast<uint32_t*>(&g_xlh[(size_t)(r0 + 8) * 128 + c]) =
                        pack_h2(acc[mt][nt][2], acc[mt][nt][3]);
            } else {
                int cc = c - 128;
                if (r0 < M)
                    *reinterpret_cast<float2*>(&g_xr[(size_t)r0 * 128 + cc]) =
                        make_float2(acc[mt][nt][0], acc[mt][nt][1]);
                if (r0 + 8 < M)
                    *reinterpret_cast<float2*>(&g_xr[(size_t)(r0 + 8) * 128 + cc]) =
                        make_float2(acc[mt][nt][2], acc[mt][nt][3]);
            }
        }
    }
}

// ---------------- GATv2 aggregation: warp/node, dual softmax states, fp16 in/out ----------------
__device__ __forceinline__ float lrelu(float v) { return v > 0.f ? v : NEG_SLOPE * v; }

__device__ __forceinline__ void osm_update(float& m, float& s, float4& acc,
                                           float eh, const float4& xlv) {
    if (eh > m) {
        float sc = __expf(m - eh);
        s *= sc;
        acc.x *= sc; acc.y *= sc; acc.z *= sc; acc.w *= sc;
        m = eh;
    }
    float w = __expf(eh - m);
    s += w;
    acc.x += w * xlv.x; acc.y += w * xlv.y;
    acc.z += w * xlv.z; acc.w += w * xlv.w;
}

__device__ __forceinline__ float4 load_xl_h(const __half* xlh, int node, int lane) {
    const uint2 raw = *reinterpret_cast<const uint2*>(&xlh[(size_t)node * HD + lane * 4]);
    float2 f0 = __half22float2(*reinterpret_cast<const __half2*>(&raw.x));
    float2 f1 = __half22float2(*reinterpret_cast<const __half2*>(&raw.y));
    return make_float4(f0.x, f0.y, f1.x, f1.y);
}

__global__ void k_aggregate(const float* __restrict__ att, const float* __restrict__ bias,
                            int outsel, int do_relu) {
    int warp = (blockIdx.x * blockDim.x + threadIdx.x) >> 5;
    if (warp >= NN) return;
    int lane = threadIdx.x & 31;
    const __half* __restrict__ xlh = g_xlh;
    __half* __restrict__ out = bufh(outsel);

    const float4 xrv  = *reinterpret_cast<const float4*>(&g_xr[(size_t)warp * HD + lane * 4]);
    const float4 attv = *reinterpret_cast<const float4*>(&att[lane * 4]);

    float m0 = -1e30f, s0 = 0.f, m1 = -1e30f, s1 = 0.f;
    float4 a0 = make_float4(0.f, 0.f, 0.f, 0.f);
    float4 a1 = make_float4(0.f, 0.f, 0.f, 0.f);

    const int beg = g_rowptr[warp];
    const int end = g_rowptr[warp + 1];

    int e = beg;
    for (; e + 1 < end; e += 2) {
        int sA = g_srcarr[e];
        int sB = g_srcarr[e + 1];
        const float4 xA = load_xl_h(xlh, sA, lane);
        const float4 xB = load_xl_h(xlh, sB, lane);

        float pA = lrelu(xA.x + xrv.x) * attv.x + lrelu(xA.y + xrv.y) * attv.y
                 + lrelu(xA.z + xrv.z) * attv.z + lrelu(xA.w + xrv.w) * attv.w;
        float pB = lrelu(xB.x + xrv.x) * attv.x + lrelu(xB.y + xrv.y) * attv.y
                 + lrelu(xB.z + xrv.z) * attv.z + lrelu(xB.w + xrv.w) * attv.w;
        pA += __shfl_xor_sync(0xffffffffu, pA, 1);
        pB += __shfl_xor_sync(0xffffffffu, pB, 1);
        pA += __shfl_xor_sync(0xffffffffu, pA, 2);
        pB += __shfl_xor_sync(0xffffffffu, pB, 2);
        pA += __shfl_xor_sync(0xffffffffu, pA, 4);
        pB += __shfl_xor_sync(0xffffffffu, pB, 4);

        osm_update(m0, s0, a0, pA, xA);
        osm_update(m1, s1, a1, pB, xB);
    }
    if (e < end) {
        int sA = g_srcarr[e];
        const float4 xA = load_xl_h(xlh, sA, lane);
        float pA = lrelu(xA.x + xrv.x) * attv.x + lrelu(xA.y + xrv.y) * attv.y
                 + lrelu(xA.z + xrv.z) * attv.z + lrelu(xA.w + xrv.w) * attv.w;
        pA += __shfl_xor_sync(0xffffffffu, pA, 1);
        pA += __shfl_xor_sync(0xffffffffu, pA, 2);
        pA += __shfl_xor_sync(0xffffffffu, pA, 4);
        osm_update(m0, s0, a0, pA, xA);
    }

    // merge the two states (exact)
    float m = fmaxf(m0, m1);
    float c0 = __expf(m0 - m);
    float c1 = (s1 > 0.f) ? __expf(m1 - m) : 0.f;
    float s = s0 * c0 + s1 * c1;
    float4 acc;
    acc.x = a0.x * c0 + a1.x * c1;
    acc.y = a0.y * c0 + a1.y * c1;
    acc.z = a0.z * c0 + a1.z * c1;
    acc.w = a0.w * c0 + a1.w * c1;

    float inv = 1.f / (s + 1e-16f);
    const float4 bv = *reinterpret_cast<const float4*>(&bias[lane * 4]);
    float4 o;
    o.x = acc.x * inv + bv.x;
    o.y = acc.y * inv + bv.y;
    o.z = acc.z * inv + bv.z;
    o.w = acc.w * inv + bv.w;
    if (do_relu) {
        o.x = fmaxf(o.x, 0.f); o.y = fmaxf(o.y, 0.f);
        o.z = fmaxf(o.z, 0.f); o.w = fmaxf(o.w, 0.f);
    }
    uint2 ov;
    ov.x = pack_h2(o.x, o.y);
    ov.y = pack_h2(o.z, o.w);
    *reinterpret_cast<uint2*>(&out[(size_t)warp * HD + lane * 4]) = ov;
}

// ---------------- pooling + classifier ----------------
__global__ void k_pool(int hsel) {
    const __half* __restrict__ h = bufh(hsel);
    int col = threadIdx.x;   // blockDim = 128
    float acc = 0.f;
    for (int r = blockIdx.x; r < NN; r += gridDim.x)
        acc += __half2float(h[(size_t)r * HD + col]);
    atomicAdd(&g_pool[col], acc);
}

__global__ void k_classify(const float* __restrict__ W, const float* __restrict__ b,
                           float* __restrict__ out) {
    int j = threadIdx.x;
    if (j < 2) {
        float s = 0.f;
        const float invn = 1.f / (float)NN;
        for (int k = 0; k < HD; k++)
            s += g_pool[k] * invn * W[k * 2 + j];
        out[j] = s + b[j];
    }
}

// ---------------- launch ----------------
extern "C" void kernel_launch(void* const* d_in, const int* in_sizes, int n_in,
                              void* d_out, int out_size) {
    const float* x  = (const float*)d_in[0];
    const int*   ei = (const int*)d_in[1];   // int32 (JAX x64 disabled)
    const float* Wl[4]  = {(const float*)d_in[2],  (const float*)d_in[6],
                           (const float*)d_in[10], (const float*)d_in[14]};
    const float* Wr[4]  = {(const float*)d_in[3],  (const float*)d_in[7],
                           (const float*)d_in[11], (const float*)d_in[15]};
    const float* att[4] = {(const float*)d_in[4],  (const float*)d_in[8],
                           (const float*)d_in[12], (const float*)d_in[16]};
    const float* bia[4] = {(const float*)d_in[5],  (const float*)d_in[9],
                           (const float*)d_in[13], (const float*)d_in[17]};
    const float* clfW = (const float*)d_in[18];
    const float* clfb = (const float*)d_in[19];
    float* out = (float*)d_out;

    const int TB = 256;
    const int gN  = (NN + TB - 1) / TB;
    const int gE  = (EE + TB - 1) / TB;
    const int gSc = (NN + 1023) / 1024;            // 49
    const int gGm = (NN + 63) / 64;                // 782 (M=64 dual-output tiles)
    const int gAg = (NN * 32 + TB - 1) / TB;       // warp per node

    // CSR build + weight conversion; layer-1 GEMM placed 4th (ncu capture window)
    k_init<<<gN, TB>>>();
    k_hist<<<gE, TB>>>(ei);
    k_wconv<<<147456 / TB, TB>>>(Wl[0], Wr[0], Wl[1], Wr[1], Wl[2], Wr[2], Wl[3], Wr[3]);
    k_gemm_dual<0><<<gGm, TB>>>(x, -1, 0, NN, FIN);          // layer 1 GEMM
    k_scan_block<<<gSc, 1024>>>();
    k_scan_top<<<1, 64>>>(gSc);
    k_finalize_csr<<<gN, TB>>>();
    k_scatter<<<gE, TB>>>(ei);

    // layer 1 aggregation
    k_aggregate<<<gAg, TB>>>(att[0], bia[0], 2, 1);
    // layer 2: A = hA(2)
    k_gemm_dual<1><<<gGm, TB>>>(nullptr, 2, 98304, NN, HD);
    k_aggregate<<<gAg, TB>>>(att[1], bia[1], 3, 1);
    // layer 3: A = hB(3)
    k_gemm_dual<1><<<gGm, TB>>>(nullptr, 3, 114688, NN, HD);
    k_aggregate<<<gAg, TB>>>(att[2], bia[2], 2, 1);
    // layer 4 (no relu): A = hA(2)
    k_gemm_dual<1><<<gGm, TB>>>(nullptr, 2, 131072, NN, HD);
    k_aggregate<<<gAg, TB>>>(att[3], bia[3], 3, 0);

    // mean-pool + classifier
    k_pool<<<512, 128>>>(3);
    k_classify<<<1, 32>>>(clfW, clfb, out);
}

// round 15
// speedup vs baseline: 1.0347x; 1.0347x over previous
#include <cuda_runtime.h>
#include <cuda_fp16.h>
#include <cstdint>

#define NN 50000
#define EE 640000
#define FIN 768
#define HD 128
#define TOT (EE + NN)
#define NEG_SLOPE 0.2f

// ---------------- scratch (device globals; no allocation allowed) ----------------
__device__ __half   g_xlh[NN * HD];   // xl fp16 (consumer: aggregation)
__device__ float    g_xr[NN * HD];
__device__ __half   g_hA[NN * HD];    // layer outputs fp16
__device__ __half   g_hB[NN * HD];
__device__ __half   g_Wh[294912];     // weights fp16 n-major: per layer [256 n][K k]
__device__ int      g_counts[NN];
__device__ int      g_local[NN];
__device__ int      g_rowptr[NN + 1];
__device__ int      g_cursor[NN];
__device__ int      g_srcarr[TOT];
__device__ int      g_blocksums[64];
__device__ float    g_pool[HD];

__device__ __forceinline__ __half* bufh(int i) {
    return i == 2 ? g_hA : g_hB;
}

__device__ __forceinline__ uint32_t pack_h2(float a, float b) {
    __half2 h = __floats2half2_rn(a, b);
    return *reinterpret_cast<uint32_t*>(&h);
}

// ---------------- CSR build ----------------
__global__ void k_init() {
    int i = blockIdx.x * blockDim.x + threadIdx.x;
    if (i < NN) g_counts[i] = 1;          // self loop
    if (i < HD) g_pool[i] = 0.f;
}

__global__ void k_hist(const int* __restrict__ ei) {
    int e = blockIdx.x * blockDim.x + threadIdx.x;
    if (e < EE) atomicAdd(&g_counts[ei[EE + e]], 1);
}

__global__ void k_scan_block() {
    __shared__ int sm[1024];
    int i = blockIdx.x * 1024 + threadIdx.x;
    int v = (i < NN) ? g_counts[i] : 0;
    sm[threadIdx.x] = v;
    __syncthreads();
    for (int off = 1; off < 1024; off <<= 1) {
        int t = (threadIdx.x >= off) ? sm[threadIdx.x - off] : 0;
        __syncthreads();
        sm[threadIdx.x] += t;
        __syncthreads();
    }
    if (i < NN) g_local[i] = sm[threadIdx.x] - v;   // exclusive
    if (threadIdx.x == 1023) g_blocksums[blockIdx.x] = sm[1023];
}

__global__ void k_scan_top(int nb) {
    __shared__ int sm[64];
    int t = threadIdx.x;
    int v = (t < nb) ? g_blocksums[t] : 0;
    sm[t] = v;
    __syncthreads();
    for (int off = 1; off < 64; off <<= 1) {
        int u = (t >= off) ? sm[t - off] : 0;
        __syncthreads();
        sm[t] += u;
        __syncthreads();
    }
    if (t < nb) g_blocksums[t] = sm[t] - v;         // exclusive
}

__global__ void k_finalize_csr() {
    int i = blockIdx.x * blockDim.x + threadIdx.x;
    if (i < NN) {
        int off = g_local[i] + g_blocksums[i >> 10];
        g_rowptr[i] = off;
        g_cursor[i] = off + 1;      // slot 0 reserved for self loop
        g_srcarr[off] = i;          // self loop
    }
    if (i == 0) g_rowptr[NN] = TOT;
}

__global__ void k_scatter(const int* __restrict__ ei) {
    int e = blockIdx.x * blockDim.x + threadIdx.x;
    if (e < EE) {
        int s = ei[e];
        int d = ei[EE + e];
        g_srcarr[atomicAdd(&g_cursor[d], 1)] = s;
    }
}

// ---------------- weight conversion: fp32 [K,128]x2 -> fp16 n-major [256][K] per layer -------
// layer bases (halfs): L1 0 (196608), L2 196608, L3 229376, L4 262144; total 294912
__global__ void k_wconv(const float* w1l, const float* w1r, const float* w2l, const float* w2r,
                        const float* w3l, const float* w3r, const float* w4l, const float* w4r) {
    int idx = blockIdx.x * blockDim.x + threadIdx.x;   // 294912 threads
    int K, base;
    const float *Wl, *Wr;
    if      (idx < 196608) { base = 0;      K = FIN; Wl = w1l; Wr = w1r; }
    else if (idx < 229376) { base = 196608; K = HD;  Wl = w2l; Wr = w2r; }
    else if (idx < 262144) { base = 229376; K = HD;  Wl = w3l; Wr = w3r; }
    else                   { base = 262144; K = HD;  Wl = w4l; Wr = w4r; }
    int local = idx - base;
    int n = local / K;
    int k = local - n * K;
    const float* W = (n < 128) ? Wl : Wr;
    g_Wh[idx] = __float2half_rn(W[k * 128 + (n & 127)]);
}

// ---------------- fp16 dual GEMM: tile M=64, N=256, ldmatrix fragments ----------------
// ASRC 0: A fp32 external; 1: A fp16 scratch. Outputs: cols 0-127 -> g_xlh, 128-255 -> g_xr.
#define ASTRH 40    // halfs per smem row (20 banks -> ldmatrix conflict-free)
#define KCH 32
// smem half offsets: A0=0, A1=2560, B0=5120, B1=15360; total 25600 halfs = 51200 B
#define SM_A(b) ((b) * 2560)
#define SM_B(b) (5120 + (b) * 10240)
#define GM_SMEM_BYTES 51200

#define LDSM4(r0, r1, r2, r3, addr) \
    asm volatile("ldmatrix.sync.aligned.m8n8.x4.shared.b16 {%0,%1,%2,%3}, [%4];" \
        : "=r"(r0), "=r"(r1), "=r"(r2), "=r"(r3) : "r"(addr))

template<int ASRC>
__global__ void __launch_bounds__(256, 2)
k_gemm_dual(const float* __restrict__ Aext, int Asel, int wbase, int M, int K) {
    extern __shared__ __half smh[];
    const float*  __restrict__ Af = Aext;
    const __half* __restrict__ Ah = (ASRC == 1) ? bufh(Asel) : nullptr;
    const __half* __restrict__ Bsrc = g_Wh + wbase;

    const int tid  = threadIdx.x;
    const int wid  = tid >> 5;
    const int lane = tid & 31;
    const int g = lane >> 2;
    const int t = lane & 3;
    const int warpM = wid & 1;   // 2 warps in M (32 rows each)
    const int warpN = wid >> 1;  // 4 warps in N (64 cols each)
    const int row0 = blockIdx.x * 64;

    const uint32_t smbase = (uint32_t)__cvta_generic_to_shared(smh);

    // ldmatrix lane-derived offsets
    const int lr  = lane & 7;
    const int lmi = lane >> 3;                 // 0..3
    const int a_row_off = lr + (lmi & 1) * 8;  // A: row within 16-tile
    const int a_k_off   = (lmi >> 1) * 8;      // A: k-half offset
    const int b_n_off   = (lmi >> 1) * 8 + lr; // B: n within 16-group
    const int b_k_off   = (lmi & 1) * 8;       // B: k-half offset

    float acc[2][8][4];
    #pragma unroll
    for (int i = 0; i < 2; i++)
        #pragma unroll
        for (int j = 0; j < 8; j++)
            #pragma unroll
            for (int k = 0; k < 4; k++) acc[i][j][k] = 0.f;

    // staging registers
    float4 raf[2];
    uint2  rah[2];
    uint4  rbu[4];

    auto loadA = [&](int k0) {
        #pragma unroll
        for (int i = 0; i < 2; i++) {
            int s = tid + i * 256;
            int r = s >> 3, q = s & 7;      // 64 rows x 8 quads (4 halfs)
            int gr = row0 + r;
            if (ASRC == 0) {
                raf[i] = (gr < M) ? *reinterpret_cast<const float4*>(&Af[(size_t)gr * K + k0 + q * 4])
                                  : make_float4(0.f, 0.f, 0.f, 0.f);
            } else {
                rah[i] = (gr < M) ? *reinterpret_cast<const uint2*>(&Ah[(size_t)gr * K + k0 + q * 4])
                                  : make_uint2(0u, 0u);
            }
        }
    };
    auto storeA = [&](int bi) {
        #pragma unroll
        for (int i = 0; i < 2; i++) {
            int s = tid + i * 256;
            int r = s >> 3, q = s & 7;
            uint2 h;
            if (ASRC == 0) { h.x = pack_h2(raf[i].x, raf[i].y); h.y = pack_h2(raf[i].z, raf[i].w); }
            else           { h = rah[i]; }
            *reinterpret_cast<uint2*>(&smh[SM_A(bi) + r * ASTRH + q * 4]) = h;
        }
    };
    auto loadB = [&](int k0) {
        #pragma unroll
        for (int i = 0; i < 4; i++) {
            int s = tid + i * 256;
            int n = s >> 2, kq = s & 3;     // 256 n x 4 octs (8 halfs)
            rbu[i] = *reinterpret_cast<const uint4*>(&Bsrc[(size_t)n * K + k0 + kq * 8]);
        }
    };
    auto storeB = [&](int bi) {
        #pragma unroll
        for (int i = 0; i < 4; i++) {
            int s = tid + i * 256;
            int n = s >> 2, kq = s & 3;
            *reinterpret_cast<uint4*>(&smh[SM_B(bi) + n * ASTRH + kq * 8]) = rbu[i];
        }
    };

    // ---- chunk 0 ----
    loadA(0); loadB(0);
    storeA(0); storeB(0);
    __syncthreads();

    const int niter = K / KCH;
    int cur = 0;
    for (int it = 0; it < niter; it++) {
        const bool has_next = (it + 1 < niter);
        if (has_next) { loadA((it + 1) * KCH); loadB((it + 1) * KCH); }

        const uint32_t saA = smbase + 2u * SM_A(cur);
        const uint32_t saB = smbase + 2u * SM_B(cur);
        #pragma unroll
        for (int ks = 0; ks < 2; ks++) {
            uint32_t af[2][4];
            #pragma unroll
            for (int mt = 0; mt < 2; mt++) {
                uint32_t addr = saA + 2u * ((warpM * 32 + mt * 16 + a_row_off) * ASTRH
                                            + a_k_off + ks * 16);
                LDSM4(af[mt][0], af[mt][1], af[mt][2], af[mt][3], addr);
            }
            uint32_t bf[8][2];
            #pragma unroll
            for (int p = 0; p < 4; p++) {
                uint32_t addr = saB + 2u * ((warpN * 64 + p * 16 + b_n_off) * ASTRH
                                            + b_k_off + ks * 16);
                LDSM4(bf[2 * p][0], bf[2 * p][1], bf[2 * p + 1][0], bf[2 * p + 1][1], addr);
            }
            #pragma unroll
            for (int mt = 0; mt < 2; mt++)
                #pragma unroll
                for (int nt = 0; nt < 8; nt++) {
                    asm volatile(
                        "mma.sync.aligned.m16n8k16.row.col.f32.f16.f16.f32 "
                        "{%0,%1,%2,%3}, {%4,%5,%6,%7}, {%8,%9}, {%0,%1,%2,%3};"
                        : "+f"(acc[mt][nt][0]), "+f"(acc[mt][nt][1]),
                          "+f"(acc[mt][nt][2]), "+f"(acc[mt][nt][3])
                        : "r"(af[mt][0]), "r"(af[mt][1]), "r"(af[mt][2]), "r"(af[mt][3]),
                          "r"(bf[nt][0]), "r"(bf[nt][1]));
                }
        }

        if (has_next) { storeA(cur ^ 1); storeB(cur ^ 1); }
        __syncthreads();
        cur ^= 1;
    }

    // epilogue: warpN 0,1 -> g_xlh (fp16); warpN 2,3 -> g_xr (fp32)
    #pragma unroll
    for (int mt = 0; mt < 2; mt++) {
        int r0 = row0 + warpM * 32 + mt * 16 + g;
        #pragma unroll
        for (int nt = 0; nt < 8; nt++) {
            int c = warpN * 64 + nt * 8 + t * 2;
            if (c < 128) {
                if (r0 < M)
                    *reinterpret_cast<uint32_t*>(&g_xlh[(size_t)r0 * 128 + c]) =
                        pack_h2(acc[mt][nt][0], acc[mt][nt][1]);
                if (r0 + 8 < M)
                    *reinterpret_cast<uint32_t*>(&g_xlh[(size_t)(r0 + 8) * 128 + c]) =
                        pack_h2(acc[mt][nt][2], acc[mt][nt][3]);
            } else {
                int cc = c - 128;
                if (r0 < M)
                    *reinterpret_cast<float2*>(&g_xr[(size_t)r0 * 128 + cc]) =
                        make_float2(acc[mt][nt][0], acc[mt][nt][1]);
                if (r0 + 8 < M)
                    *reinterpret_cast<float2*>(&g_xr[(size_t)(r0 + 8) * 128 + cc]) =
                        make_float2(acc[mt][nt][2], acc[mt][nt][3]);
            }
        }
    }
}

// ---------------- GATv2 aggregation: warp/node, dual softmax states, fp16 in/out ----------------
__device__ __forceinline__ float lrelu(float v) { return v > 0.f ? v : NEG_SLOPE * v; }

__device__ __forceinline__ void osm_update(float& m, float& s, float4& acc,
                                           float eh, const float4& xlv) {
    if (eh > m) {
        float sc = __expf(m - eh);
        s *= sc;
        acc.x *= sc; acc.y *= sc; acc.z *= sc; acc.w *= sc;
        m = eh;
    }
    float w = __expf(eh - m);
    s += w;
    acc.x += w * xlv.x; acc.y += w * xlv.y;
    acc.z += w * xlv.z; acc.w += w * xlv.w;
}

__device__ __forceinline__ float4 load_xl_h(const __half* xlh, int node, int lane) {
    const uint2 raw = *reinterpret_cast<const uint2*>(&xlh[(size_t)node * HD + lane * 4]);
    float2 f0 = __half22float2(*reinterpret_cast<const __half2*>(&raw.x));
    float2 f1 = __half22float2(*reinterpret_cast<const __half2*>(&raw.y));
    return make_float4(f0.x, f0.y, f1.x, f1.y);
}

__global__ void k_aggregate(const float* __restrict__ att, const float* __restrict__ bias,
                            int outsel, int do_relu) {
    int warp = (blockIdx.x * blockDim.x + threadIdx.x) >> 5;
    if (warp >= NN) return;
    int lane = threadIdx.x & 31;
    const __half* __restrict__ xlh = g_xlh;
    __half* __restrict__ out = bufh(outsel);

    const float4 xrv  = *reinterpret_cast<const float4*>(&g_xr[(size_t)warp * HD + lane * 4]);
    const float4 attv = *reinterpret_cast<const float4*>(&att[lane * 4]);

    float m0 = -1e30f, s0 = 0.f, m1 = -1e30f, s1 = 0.f;
    float4 a0 = make_float4(0.f, 0.f, 0.f, 0.f);
    float4 a1 = make_float4(0.f, 0.f, 0.f, 0.f);

    const int beg = g_rowptr[warp];
    const int end = g_rowptr[warp + 1];

    int e = beg;
    for (; e + 1 < end; e += 2) {
        int sA = g_srcarr[e];
        int sB = g_srcarr[e + 1];
        const float4 xA = load_xl_h(xlh, sA, lane);
        const float4 xB = load_xl_h(xlh, sB, lane);

        float pA = lrelu(xA.x + xrv.x) * attv.x + lrelu(xA.y + xrv.y) * attv.y
                 + lrelu(xA.z + xrv.z) * attv.z + lrelu(xA.w + xrv.w) * attv.w;
        float pB = lrelu(xB.x + xrv.x) * attv.x + lrelu(xB.y + xrv.y) * attv.y
                 + lrelu(xB.z + xrv.z) * attv.z + lrelu(xB.w + xrv.w) * attv.w;
        pA += __shfl_xor_sync(0xffffffffu, pA, 1);
        pB += __shfl_xor_sync(0xffffffffu, pB, 1);
        pA += __shfl_xor_sync(0xffffffffu, pA, 2);
        pB += __shfl_xor_sync(0xffffffffu, pB, 2);
        pA += __shfl_xor_sync(0xffffffffu, pA, 4);
        pB += __shfl_xor_sync(0xffffffffu, pB, 4);

        osm_update(m0, s0, a0, pA, xA);
        osm_update(m1, s1, a1, pB, xB);
    }
    if (e < end) {
        int sA = g_srcarr[e];
        const float4 xA = load_xl_h(xlh, sA, lane);
        float pA = lrelu(xA.x + xrv.x) * attv.x + lrelu(xA.y + xrv.y) * attv.y
                 + lrelu(xA.z + xrv.z) * attv.z + lrelu(xA.w + xrv.w) * attv.w;
        pA += __shfl_xor_sync(0xffffffffu, pA, 1);
        pA += __shfl_xor_sync(0xffffffffu, pA, 2);
        pA += __shfl_xor_sync(0xffffffffu, pA, 4);
        osm_update(m0, s0, a0, pA, xA);
    }

    // merge the two states (exact)
    float m = fmaxf(m0, m1);
    float c0 = __expf(m0 - m);
    float c1 = (s1 > 0.f) ? __expf(m1 - m) : 0.f;
    float s = s0 * c0 + s1 * c1;
    float4 acc;
    acc.x = a0.x * c0 + a1.x * c1;
    acc.y = a0.y * c0 + a1.y * c1;
    acc.z = a0.z * c0 + a1.z * c1;
    acc.w = a0.w * c0 + a1.w * c1;

    float inv = 1.f / (s + 1e-16f);
    const float4 bv = *reinterpret_cast<const float4*>(&bias[lane * 4]);
    float4 o;
    o.x = acc.x * inv + bv.x;
    o.y = acc.y * inv + bv.y;
    o.z = acc.z * inv + bv.z;
    o.w = acc.w * inv + bv.w;
    if (do_relu) {
        o.x = fmaxf(o.x, 0.f); o.y = fmaxf(o.y, 0.f);
        o.z = fmaxf(o.z, 0.f); o.w = fmaxf(o.w, 0.f);
    }
    uint2 ov;
    ov.x = pack_h2(o.x, o.y);
    ov.y = pack_h2(o.z, o.w);
    *reinterpret_cast<uint2*>(&out[(size_t)warp * HD + lane * 4]) = ov;
}

// ---------------- pooling + classifier ----------------
__global__ void k_pool(int hsel) {
    const __half* __restrict__ h = bufh(hsel);
    int col = threadIdx.x;   // blockDim = 128
    float acc = 0.f;
    for (int r = blockIdx.x; r < NN; r += gridDim.x)
        acc += __half2float(h[(size_t)r * HD + col]);
    atomicAdd(&g_pool[col], acc);
}

__global__ void k_classify(const float* __restrict__ W, const float* __restrict__ b,
                           float* __restrict__ out) {
    int j = threadIdx.x;
    if (j < 2) {
        float s = 0.f;
        const float invn = 1.f / (float)NN;
        for (int k = 0; k < HD; k++)
            s += g_pool[k] * invn * W[k * 2 + j];
        out[j] = s + b[j];
    }
}

// ---------------- launch ----------------
extern "C" void kernel_launch(void* const* d_in, const int* in_sizes, int n_in,
                              void* d_out, int out_size) {
    const float* x  = (const float*)d_in[0];
    const int*   ei = (const int*)d_in[1];   // int32 (JAX x64 disabled)
    const float* Wl[4]  = {(const float*)d_in[2],  (const float*)d_in[6],
                           (const float*)d_in[10], (const float*)d_in[14]};
    const float* Wr[4]  = {(const float*)d_in[3],  (const float*)d_in[7],
                           (const float*)d_in[11], (const float*)d_in[15]};
    const float* att[4] = {(const float*)d_in[4],  (const float*)d_in[8],
                           (const float*)d_in[12], (const float*)d_in[16]};
    const float* bia[4] = {(const float*)d_in[5],  (const float*)d_in[9],
                           (const float*)d_in[13], (const float*)d_in[17]};
    const float* clfW = (const float*)d_in[18];
    const float* clfb = (const float*)d_in[19];
    float* out = (float*)d_out;

    cudaFuncSetAttribute(k_gemm_dual<0>, cudaFuncAttributeMaxDynamicSharedMemorySize,
                         GM_SMEM_BYTES);
    cudaFuncSetAttribute(k_gemm_dual<1>, cudaFuncAttributeMaxDynamicSharedMemorySize,
                         GM_SMEM_BYTES);

    const int TB = 256;
    const int gN  = (NN + TB - 1) / TB;
    const int gE  = (EE + TB - 1) / TB;
    const int gSc = (NN + 1023) / 1024;            // 49
    const int gGm = (NN + 63) / 64;                // 782 (M=64 dual-output tiles)
    const int gAg = (NN * 32 + TB - 1) / TB;       // warp per node

    // CSR build + weight conversion; layer-1 GEMM placed 4th (ncu capture window)
    k_init<<<gN, TB>>>();
    k_hist<<<gE, TB>>>(ei);
    k_wconv<<<294912 / TB, TB>>>(Wl[0], Wr[0], Wl[1], Wr[1], Wl[2], Wr[2], Wl[3], Wr[3]);
    k_gemm_dual<0><<<gGm, TB, GM_SMEM_BYTES>>>(x, -1, 0, NN, FIN);   // layer 1 GEMM
    k_scan_block<<<gSc, 1024>>>();
    k_scan_top<<<1, 64>>>(gSc);
    k_finalize_csr<<<gN, TB>>>();
    k_scatter<<<gE, TB>>>(ei);

    // layer 1 aggregation
    k_aggregate<<<gAg, TB>>>(att[0], bia[0], 2, 1);
    // layer 2: A = hA(2)
    k_gemm_dual<1><<<gGm, TB, GM_SMEM_BYTES>>>(nullptr, 2, 196608, NN, HD);
    k_aggregate<<<gAg, TB>>>(att[1], bia[1], 3, 1);
    // layer 3: A = hB(3)
    k_gemm_dual<1><<<gGm, TB, GM_SMEM_BYTES>>>(nullptr, 3, 229376, NN, HD);
    k_aggregate<<<gAg, TB>>>(att[2], bia[2], 2, 1);
    // layer 4 (no relu): A = hA(2)
    k_gemm_dual<1><<<gGm, TB, GM_SMEM_BYTES>>>(nullptr, 2, 262144, NN, HD);
    k_aggregate<<<gAg, TB>>>(att[3], bia[3], 3, 0);

    // mean-pool + classifier
    k_pool<<<512, 128>>>(3);
    k_classify<<<1, 32>>>(clfW, clfb, out);
}